// round 13
// baseline (speedup 1.0000x reference)
#include <cuda_runtime.h>
#include <math.h>

#define B_    8
#define P_    19248
#define C_    81
#define NOBJ_ 8
#define KC_   32
#define PH_   138
#define PW_   138
#define HH_   550
#define WW_   550
#define NPIX_ (PH_*PW_)
#define MTT_  100
#define SEG3  38   // ceil(P_/512)
#define MBLK  76   // ceil(P_/256)

#define RES_BLOCKS   (B_*PH_)                 // 1104
#define MATCH_BLOCKS (B_*MBLK)                // 608
#define LSE_BLOCKS   ((B_*P_)/8)              // 19248
#define BIG_BLOCKS   (RES_BLOCKS + MATCH_BLOCKS + LSE_BLOCKS)

#define PLBLK        38                       // ceil(P_/512) posloss blocks per batch
#define SP_BLOCKS    (16 + B_*PLBLK)          // 16 selpick + 304 posloss

// ------------------------- device scratch (static) -------------------------
__device__ double             g_acc[2];
__device__ double             g_mlsum[B_];
__device__ unsigned long long g_boxkey[B_][NOBJ_];
__device__ int                g_conf[B_][P_];
__device__ unsigned char      g_pmi[B_][P_];
__device__ float              g_mark[B_][P_];
__device__ float              g_lse[B_][P_];
__device__ int                g_numpos[B_];
__device__ unsigned char      g_dm[B_][NPIX_];
__device__ float              g_wts[PH_][9];
__device__ int                g_wi0[PH_];
__device__ int                g_ones[B_][NOBJ_];
__device__ int                g_sel[B_][MTT_];
__device__ int                g_selcnt[B_];
__device__ int4               g_rect[B_][MTT_];
__device__ float              g_invd[B_][MTT_];
__device__ int                g_obit[B_][MTT_];

// ------------------------- helpers -------------------------
__device__ __forceinline__ float bRedF256(float v) {
    __shared__ float sd[8];
    int ln = threadIdx.x & 31, wd = threadIdx.x >> 5;
    #pragma unroll
    for (int o = 16; o; o >>= 1) v += __shfl_down_sync(0xffffffffu, v, o);
    if (ln == 0) sd[wd] = v;
    __syncthreads();
    v = (threadIdx.x < 8) ? sd[threadIdx.x] : 0.f;
    if (wd == 0) {
        #pragma unroll
        for (int o = 4; o; o >>= 1) v += __shfl_down_sync(0xffffffffu, v, o);
        if (ln == 0) sd[0] = v;
    }
    __syncthreads();
    float r = sd[0];
    __syncthreads();
    return r;
}
__device__ __forceinline__ float bRedF512(float v) {
    __shared__ float sd[16];
    int ln = threadIdx.x & 31, wd = threadIdx.x >> 5;
    #pragma unroll
    for (int o = 16; o; o >>= 1) v += __shfl_down_sync(0xffffffffu, v, o);
    if (ln == 0) sd[wd] = v;
    __syncthreads();
    v = (threadIdx.x < 16) ? sd[threadIdx.x] : 0.f;
    if (wd == 0) {
        #pragma unroll
        for (int o = 8; o; o >>= 1) v += __shfl_down_sync(0xffffffffu, v, o);
        if (ln == 0) sd[0] = v;
    }
    __syncthreads();
    float r = sd[0];
    __syncthreads();
    return r;
}
__device__ __forceinline__ int bRedI512(int v) {
    __shared__ int si[16];
    int ln = threadIdx.x & 31, wd = threadIdx.x >> 5;
    #pragma unroll
    for (int o = 16; o; o >>= 1) v += __shfl_down_sync(0xffffffffu, v, o);
    if (ln == 0) si[wd] = v;
    __syncthreads();
    v = (threadIdx.x < 16) ? si[threadIdx.x] : 0;
    if (wd == 0) {
        #pragma unroll
        for (int o = 8; o; o >>= 1) v += __shfl_down_sync(0xffffffffu, v, o);
        if (ln == 0) si[0] = v;
    }
    __syncthreads();
    int r = si[0];
    __syncthreads();
    return r;
}
__device__ __forceinline__ int bScanEx512(int v, int* sh) {
    int tid = threadIdx.x;
    sh[tid] = v;
    __syncthreads();
    #pragma unroll
    for (int off = 1; off < 512; off <<= 1) {
        int t = (tid >= off) ? sh[tid - off] : 0;
        __syncthreads();
        sh[tid] += t;
        __syncthreads();
    }
    int incl = sh[tid];
    __syncthreads();
    return incl - v;
}

// ------------------------- K0: init (weights + zero accumulators) -------------------------
__global__ void k_init() {
    int t = threadIdx.x;
    if (t < PH_) {
        float inv = (float)(1.0 / (138.0 / 550.0));
        float s = ((float)t + 0.5f) * inv - 0.5f;
        int i0 = (int)ceilf(s - inv);
        int i1 = (int)floorf(s + inv);
        if (i0 < 0) i0 = 0;
        if (i1 > HH_ - 1) i1 = HH_ - 1;
        int cnt = i1 - i0 + 1; if (cnt > 9) cnt = 9;
        float w[9]; float wsum = 0.f;
        #pragma unroll
        for (int k = 0; k < 9; k++) {
            float x = __fdiv_rn(fabsf((float)(i0 + k) - s), inv);
            float wv = fmaxf(0.f, 1.f - x);
            if (k >= cnt) wv = 0.f;
            w[k] = wv; wsum += wv;
        }
        #pragma unroll
        for (int k = 0; k < 9; k++) g_wts[t][k] = __fdiv_rn(w[k], wsum);
        g_wi0[t] = i0;
    }
    if (t < B_ * NOBJ_) {
        ((unsigned long long*)g_boxkey)[t] = 0ull;
        ((int*)g_ones)[t] = 0;
    }
    if (t < B_) { g_numpos[t] = 0; g_mlsum[t] = 0.0; g_selcnt[t] = 0; }
    if (t < 2) g_acc[t] = 0.0;
}

// ------------------------- K1: fused resize + match + lse -------------------------
__global__ void __launch_bounds__(256) k_big(const float* __restrict__ mg,
                                             const float* __restrict__ priors,
                                             const float* __restrict__ box_gt,
                                             const int* __restrict__ class_gt,
                                             const float* __restrict__ class_p) {
    int blk = blockIdx.x;
    int tid = threadIdx.x;
    if (blk < RES_BLOCKS) {
        // ================= resize role =================
        __shared__ float srow[NOBJ_][WW_];
        __shared__ int shc[NOBJ_];
        int b  = blk / PH_;
        int yo = blk % PH_;
        int w  = tid >> 5;
        int lane = tid & 31;
        int i0 = g_wi0[yo];
        float wy[9];
        #pragma unroll
        for (int t = 0; t < 9; t++) wy[t] = g_wts[yo][t];
        if (tid < NOBJ_) shc[tid] = 0;

        const float* src = mg + ((size_t)(b * NOBJ_ + w)) * HH_ * WW_;
        const float2* rows2[9];
        #pragma unroll
        for (int t = 0; t < 9; t++) {
            int yi = i0 + t; if (yi > HH_ - 1) yi = HH_ - 1;
            rows2[t] = (const float2*)(src + (size_t)yi * WW_);
        }
        float2* drow = (float2*)&srow[w][0];
        #pragma unroll 2
        for (int c = lane; c < WW_ / 2; c += 32) {
            float ax = 0.f, ay = 0.f;
            #pragma unroll
            for (int t = 0; t < 9; t++) {
                float2 v = rows2[t][c];
                ax += wy[t] * v.x;
                ay += wy[t] * v.y;
            }
            float2 o2; o2.x = ax; o2.y = ay;
            drow[c] = o2;
        }
        __syncthreads();

        unsigned bits = 0;
        if (tid < PW_) {
            int j0 = g_wi0[tid];
            float wx[9];
            #pragma unroll
            for (int t = 0; t < 9; t++) wx[t] = g_wts[tid][t];
            #pragma unroll
            for (int o = 0; o < NOBJ_; o++) {
                float s = 0.f;
                #pragma unroll
                for (int t = 0; t < 9; t++) {
                    int xi = j0 + t; if (xi > WW_ - 1) xi = WW_ - 1;
                    s += wx[t] * srow[o][xi];
                }
                if (s > 0.5f) bits |= (1u << o);
            }
            g_dm[b][yo * PW_ + tid] = (unsigned char)bits;
        }
        #pragma unroll
        for (int o = 0; o < NOBJ_; o++) {
            unsigned mb = __ballot_sync(0xffffffffu, (bits >> o) & 1);
            if (lane == 0 && mb) atomicAdd(&shc[o], __popc(mb));
        }
        __syncthreads();
        if (tid < NOBJ_ && shc[tid]) atomicAdd(&g_ones[b][tid], shc[tid]);
    } else if (blk < RES_BLOCKS + MATCH_BLOCKS) {
        // ================= match role =================
        int id = blk - RES_BLOCKS;
        int b = id / MBLK;
        int p = (id % MBLK) * 256 + tid;
        bool valid = p < P_;
        int lane = tid & 31;
        __shared__ float sbg[NOBJ_][4];
        __shared__ unsigned long long skey[NOBJ_];
        if (tid < NOBJ_ * 4) ((float*)sbg)[tid] = box_gt[b * NOBJ_ * 4 + tid];
        if (tid < NOBJ_) skey[tid] = 0ull;
        __syncthreads();

        float dx1 = 0.f, dy1 = 0.f, dx2 = 0.f, dy2 = 0.f, areaP = 0.f;
        if (valid) {
            float4 pr = ((const float4*)priors)[p];
            float w2 = __fmul_rn(pr.z, 0.5f), h2 = __fmul_rn(pr.w, 0.5f);
            dx1 = __fsub_rn(pr.x, w2); dy1 = __fsub_rn(pr.y, h2);
            dx2 = __fadd_rn(pr.x, w2); dy2 = __fadd_rn(pr.y, h2);
            areaP = __fmul_rn(__fsub_rn(dx2, dx1), __fsub_rn(dy2, dy1));
        }
        float best = -1.f; int besto = 0;
        #pragma unroll
        for (int o = 0; o < NOBJ_; o++) {
            unsigned u = 0u;
            if (valid) {
                float gx1 = sbg[o][0], gy1 = sbg[o][1], gx2 = sbg[o][2], gy2 = sbg[o][3];
                float ix = fmaxf(__fsub_rn(fminf(gx2, dx2), fmaxf(gx1, dx1)), 0.f);
                float iy = fmaxf(__fsub_rn(fminf(gy2, dy2), fmaxf(gy1, dy1)), 0.f);
                float inter = __fmul_rn(ix, iy);
                float areaG = __fmul_rn(__fsub_rn(gx2, gx1), __fsub_rn(gy2, gy1));
                float iou = __fdiv_rn(inter, __fsub_rn(__fadd_rn(areaG, areaP), inter));
                if (iou > best) { best = iou; besto = o; }
                u = __float_as_uint(iou);
            }
            unsigned wmax = __reduce_max_sync(0xffffffffu, u);
            unsigned bal = __ballot_sync(0xffffffffu, u == wmax);
            int leader = __ffs(bal) - 1;
            if (lane == leader && valid)
                atomicMax(&skey[o], (((unsigned long long)u) << 32)
                                   | (unsigned long long)(0xFFFFFFFFu - (unsigned)p));
        }
        if (valid) {
            int cg = class_gt[b * NOBJ_ + besto];
            int cf = cg + 1;
            if (best < 0.5f) cf = -1;
            if (best < 0.4f) cf = 0;
            g_conf[b][p] = cf;
            g_pmi[b][p]  = (unsigned char)besto;
        }
        __syncthreads();
        if (tid < NOBJ_ && skey[tid]) atomicMax(&g_boxkey[b][tid], skey[tid]);
    } else {
        // ================= lse role =================
        int gw = (blk - RES_BLOCKS - MATCH_BLOCKS) * 8 + (tid >> 5);
        int lane = tid & 31;
        const float* xp = class_p + (size_t)gw * C_;
        float v0 = xp[lane];
        float v1 = xp[lane + 32];
        float v2 = (lane < C_ - 64) ? xp[lane + 64] : 0.f;
        float s = __expf(v0) + __expf(v1);
        if (lane < C_ - 64) s += __expf(v2);
        #pragma unroll
        for (int off = 16; off; off >>= 1) s += __shfl_xor_sync(0xffffffffu, s, off);
        float lse = __logf(s);
        float x0 = __shfl_sync(0xffffffffu, v0, 0);
        if (lane == 0) {
            int b = gw / P_, p = gw % P_;
            g_lse[b][p]  = lse;
            g_mark[b][p] = lse - x0;
        }
    }
}

// ------------------------- K2: forced matches -------------------------
__global__ void k_override(const int* __restrict__ class_gt) {
    int b = threadIdx.x;
    if (b < B_) {
        for (int o = 0; o < NOBJ_; o++) {
            unsigned long long k = g_boxkey[b][o];
            unsigned p = 0xFFFFFFFFu - (unsigned)(k & 0xFFFFFFFFull);
            g_conf[b][p] = class_gt[b * NOBJ_ + o] + 1;
            g_pmi[b][p]  = (unsigned char)o;
        }
    }
}

// ------------------------- K3: select(8) + pick(8) + posloss(304), NO dynamic smem -------------------------
__global__ void __launch_bounds__(512) k_selpick(const float* __restrict__ box_gt,
                                                 const float* __restrict__ class_p,
                                                 const float* __restrict__ box_p,
                                                 const float* __restrict__ priors) {
    __shared__ int hist[256];
    __shared__ int sscan[512];
    __shared__ unsigned sh_prefix;
    __shared__ int sh_rem;
    int tid = threadIdx.x;

    if (blockIdx.x < 8) {
        // ===== select role: masks g_mark in place, then radix over global =====
        int b = blockIdx.x;
        float* mk = &g_mark[b][0];
        const int* cfp = &g_conf[b][0];
        int npl = 0;
        for (int p = tid; p < P_; p += 512) {
            int cf = cfp[p];
            float v = (cf == 0) ? mk[p] : 0.f;
            mk[p] = v;
            if (cf > 0) npl++;
        }
        int np = bRedI512(npl);   // syncthreads inside: write-back visible to block
        long long kll = 3LL * np; if (kll > P_ - 1) kll = P_ - 1;
        if (kll <= 0) return;
        if (tid == 0) { sh_prefix = 0u; sh_rem = (int)kll; }
        __syncthreads();

        for (int pass = 0; pass < 4; pass++) {
            int shift = 24 - 8 * pass;
            unsigned himask = (pass == 0) ? 0u : (0xFFFFFFFFu << (shift + 8));
            if (tid < 256) hist[tid] = 0;
            __syncthreads();
            unsigned pref = sh_prefix;
            for (int p = tid; p < P_; p += 512) {
                unsigned u = __float_as_uint(mk[p]);
                if ((u & himask) == pref)
                    atomicAdd(&hist[(u >> shift) & 255], 1);
            }
            __syncthreads();
            if (tid == 0) {
                int rem = sh_rem;
                int cum = 0, bin = 255;
                for (; bin > 0; bin--) {
                    cum += hist[bin];
                    if (cum >= rem) break;
                }
                if (cum < rem) cum += hist[0];
                sh_rem = rem - (cum - hist[bin]);
                sh_prefix = pref | ((unsigned)bin << shift);
            }
            __syncthreads();
        }
        unsigned tb = sh_prefix;
        int quota = sh_rem;

        float sgt = 0.f, seq = 0.f; int ceq = 0;
        for (int p = tid; p < P_; p += 512) {
            float v = mk[p];
            unsigned u = __float_as_uint(v);
            if (u > tb) sgt += v;
            else if (u == tb) { seq += v; ceq++; }
        }
        float sgt_t = bRedF512(sgt);
        float seq_t = bRedF512(seq);
        int   ceq_t = bRedI512(ceq);
        bool ordered = (ceq_t != quota) && (tb != 0u);
        if (tid == 0) atomicAdd(&g_acc[1], (double)(sgt_t + (ordered ? 0.f : seq_t)));

        if (ordered) {
            int s0 = tid * SEG3, s1 = s0 + SEG3; if (s1 > P_) s1 = P_;
            int c = 0;
            for (int p = s0; p < s1; p++)
                if (__float_as_uint(mk[p]) == tb) c++;
            int pre = bScanEx512(c, sscan);
            float sord = 0.f; int r = pre;
            for (int p = s0; p < s1; p++) {
                if (__float_as_uint(mk[p]) == tb) {
                    if (r < quota) sord += mk[p];
                    r++;
                }
            }
            float st = bRedF512(sord);
            if (tid == 0) atomicAdd(&g_acc[1], (double)st);
        }
    } else if (blockIdx.x < 16) {
        // ===== pick role (computes its own numpos) =====
        int b = blockIdx.x - 8;
        int s0 = tid * SEG3, s1 = s0 + SEG3; if (s1 > P_) s1 = P_;
        int c = 0;
        for (int p = s0; p < s1; p++)
            if (g_conf[b][p] > 0) c++;
        int pre = bScanEx512(c, sscan);
        int np = sscan[511];
        int cap = np < MTT_ ? np : MTT_;
        if (tid == 0) { g_numpos[b] = np; g_selcnt[b] = cap; }
        int r = pre;
        for (int p = s0; p < s1; p++) {
            if (g_conf[b][p] > 0) {
                if (r < cap) g_sel[b][r] = p;
                r++;
            }
        }
        __syncthreads();
        for (int k = tid; k < cap; k += 512) {
            int p = g_sel[b][k];
            int o = g_pmi[b][p];
            const float* bg = box_gt + (size_t)(b * NOBJ_ + o) * 4;
            float bx1 = bg[0], by1 = bg[1], bx2 = bg[2], by2 = bg[3];
            float ax = bx1 * 138.f, bx = bx2 * 138.f;
            float x1 = fminf(ax, bx), x2 = fmaxf(ax, bx);
            x1 = fmaxf(x1 - 1.f, 0.f); x2 = fminf(x2 + 1.f, 138.f);
            float ay = by1 * 138.f, by = by2 * 138.f;
            float y1 = fminf(ay, by), y2 = fmaxf(ay, by);
            y1 = fmaxf(y1 - 1.f, 0.f); y2 = fminf(y2 + 1.f, 138.f);
            int xlo = (int)ceilf(x1), xhi = (int)ceilf(x2);
            int ylo = (int)ceilf(y1), yhi = (int)ceilf(y2);
            if (xlo < 0) xlo = 0; if (xhi > PW_) xhi = PW_;
            if (ylo < 0) ylo = 0; if (yhi > PH_) yhi = PH_;
            int4 r4; r4.x = xlo; r4.y = xhi; r4.z = ylo; r4.w = yhi;
            g_rect[b][k] = r4;
            double denom = (double)((bx2 - bx1) * (by2 - by1));
            g_invd[b][k] = (float)(1.0 / denom);
            g_obit[b][k] = o;
        }
    } else {
        // ===== posloss role: 512 active threads per block =====
        int id = blockIdx.x - 16;
        int b = id / PLBLK;
        int p = (id % PLBLK) * 512 + tid;
        int lane = tid & 31;
        bool pos = false;
        int cf = 0;
        if (p < P_) { cf = g_conf[b][p]; pos = cf > 0; }

        float lb = 0.f, nll = 0.f;
        if (pos) {
            float lse = g_lse[b][p];
            float xt = class_p[((size_t)(b * P_ + p)) * C_ + cf];
            nll = lse - xt;
            int o = g_pmi[b][p];
            const float* bg = box_gt + (size_t)(b * NOBJ_ + o) * 4;
            float mnx = bg[0], mny = bg[1], mxx = bg[2], mxy = bg[3];
            float4 pr = ((const float4*)priors)[p];
            float off0 = __fdiv_rn(__fsub_rn(__fmul_rn(__fadd_rn(mnx, mxx), 0.5f), pr.x), __fmul_rn(0.1f, pr.z));
            float off1 = __fdiv_rn(__fsub_rn(__fmul_rn(__fadd_rn(mny, mxy), 0.5f), pr.y), __fmul_rn(0.1f, pr.w));
            float off2 = __fdiv_rn(logf(__fdiv_rn(__fsub_rn(mxx, mnx), pr.z)), 0.2f);
            float off3 = __fdiv_rn(logf(__fdiv_rn(__fsub_rn(mxy, mny), pr.w)), 0.2f);
            const float4 bp = ((const float4*)box_p)[b * P_ + p];
            float d;
            d = fabsf(bp.x - off0); lb += (d < 1.f) ? 0.5f*d*d : d - 0.5f;
            d = fabsf(bp.y - off1); lb += (d < 1.f) ? 0.5f*d*d : d - 0.5f;
            d = fabsf(bp.z - off2); lb += (d < 1.f) ? 0.5f*d*d : d - 0.5f;
            d = fabsf(bp.w - off3); lb += (d < 1.f) ? 0.5f*d*d : d - 0.5f;
        }
        unsigned bal = __ballot_sync(0xffffffffu, pos);
        #pragma unroll
        for (int off = 16; off; off >>= 1) {
            lb  += __shfl_down_sync(0xffffffffu, lb, off);
            nll += __shfl_down_sync(0xffffffffu, nll, off);
        }
        if (lane == 0 && bal) {
            atomicAdd(&g_acc[0], (double)lb);
            atomicAdd(&g_acc[1], (double)nll);
        }
    }
}

// ------------------------- K4: mask BCE, pixel-centric -------------------------
__global__ void __launch_bounds__(256) k_mask(const float* __restrict__ proto_p,
                                              const float* __restrict__ coef_p) {
    __shared__ float4 scoef[MTT_][8];
    __shared__ int4   srect[MTT_];
    __shared__ float  sinv[MTT_];
    __shared__ int    sob[MTT_];
    int b = blockIdx.y;
    int tid = threadIdx.x;
    int px = blockIdx.x * 256 + tid;
    int cnt = g_selcnt[b];

    for (int i = tid; i < cnt * 8; i += 256) {
        int k = i >> 3, q = i & 7;
        int p = g_sel[b][k];
        scoef[k][q] = ((const float4*)(coef_p + ((size_t)(b * P_ + p)) * KC_))[q];
    }
    for (int i = tid; i < cnt; i += 256) {
        srect[i] = g_rect[b][i];
        sinv[i]  = g_invd[b][i];
        sob[i]   = g_obit[b][i];
    }
    __syncthreads();

    float acc = 0.f;
    if (px < NPIX_ && cnt > 0) {
        int y = px / PW_, x = px % PW_;
        const float4* pp = (const float4*)(proto_p + (size_t)(b * NPIX_ + px) * KC_);
        float4 r0 = pp[0], r1 = pp[1], r2 = pp[2], r3 = pp[3];
        float4 r4 = pp[4], r5 = pp[5], r6 = pp[6], r7 = pp[7];
        unsigned dmb = g_dm[b][px];
        const float L = 16.118095651f;
        const float A  = -logf(1e-7f);
        const float Bc = -log1pf(-1e-7f);
        for (int k = 0; k < cnt; k++) {
            int4 r = srect[k];
            if (x >= r.x && x < r.y && y >= r.z && y < r.w) {
                const float4* ck = scoef[k];
                float4 c0 = ck[0], c1 = ck[1], c2 = ck[2], c3 = ck[3];
                float4 c4 = ck[4], c5 = ck[5], c6 = ck[6], c7 = ck[7];
                float z =
                    r0.x*c0.x + r0.y*c0.y + r0.z*c0.z + r0.w*c0.w +
                    r1.x*c1.x + r1.y*c1.y + r1.z*c1.z + r1.w*c1.w +
                    r2.x*c2.x + r2.y*c2.y + r2.z*c2.z + r2.w*c2.w +
                    r3.x*c3.x + r3.y*c3.y + r3.z*c3.z + r3.w*c3.w +
                    r4.x*c4.x + r4.y*c4.y + r4.z*c4.z + r4.w*c4.w +
                    r5.x*c5.x + r5.y*c5.y + r5.z*c5.z + r5.w*c5.w +
                    r6.x*c6.x + r6.y*c6.y + r6.z*c6.z + r6.w*c6.w +
                    r7.x*c7.x + r7.y*c7.y + r7.z*c7.z + r7.w*c7.w;
                float zc = fminf(fmaxf(z, -L), L);
                float sp = fmaxf(zc, 0.f) + __logf(1.f + __expf(-fabsf(zc)));
                int gt = (dmb >> sob[k]) & 1;
                float vp = sp - (gt ? (zc + A) : Bc);
                acc += vp * sinv[k];
            }
        }
    }
    float t = bRedF256(acc);
    if (tid == 0) atomicAdd(&g_mlsum[b], (double)t);
}

// ------------------------- K5: final combine -------------------------
__global__ void __launch_bounds__(256) k_final(float* out) {
    __shared__ double sd[8];
    int tid = threadIdx.x;
    const float A  = -logf(1e-7f);
    const float Bc = -log1pf(-1e-7f);
    double acc = 0.0;
    for (int i = tid; i < B_ * MTT_; i += 256) {
        int b = i / MTT_, k = i % MTT_;
        if (k < g_selcnt[b]) {
            int o = g_obit[b][k];
            int ones = g_ones[b][o];
            double c = (double)ones * (double)A + (double)(NPIX_ - ones) * (double)Bc;
            int np = g_numpos[b];
            double s = 1.0;
            if (np > MTT_) {
                float npf = (float)np;
                s = (double)(npf / fmaxf(fminf(npf, (float)MTT_), 1.f));
            }
            acc += c * (double)g_invd[b][k] * s;
        }
    }
    if (tid < B_) {
        int np = g_numpos[tid];
        double s = 1.0;
        if (np > MTT_) {
            float npf = (float)np;
            s = (double)(npf / fmaxf(fminf(npf, (float)MTT_), 1.f));
        }
        acc += g_mlsum[tid] * s;
    }
    int ln = tid & 31, wd = tid >> 5;
    #pragma unroll
    for (int o = 16; o; o >>= 1) acc += __shfl_down_sync(0xffffffffu, acc, o);
    if (ln == 0) sd[wd] = acc;
    __syncthreads();
    if (tid < 8) {
        acc = sd[tid];
        #pragma unroll
        for (int o = 4; o; o >>= 1) acc += __shfl_down_sync(0xffffffffu, acc, o);
        if (tid == 0) {
            double total = 1.5 * g_acc[0] + g_acc[1] + acc * 6.125 / 138.0 / 138.0;
            out[0] = (float)total;
        }
    }
}

// ------------------------- launch: 6-node linear chain -------------------------
extern "C" void kernel_launch(void* const* d_in, const int* in_sizes, int n_in,
                              void* d_out, int out_size) {
    const float* class_p  = (const float*)d_in[0];
    const float* box_p    = (const float*)d_in[1];
    const float* coef_p   = (const float*)d_in[2];
    const float* proto_p  = (const float*)d_in[3];
    const float* priors   = (const float*)d_in[4];
    const float* box_gt   = (const float*)d_in[5];
    const float* mask_gt  = (const float*)d_in[6];
    const int*   class_gt = (const int*)d_in[7];
    float* out = (float*)d_out;

    k_init<<<1, 256>>>();
    k_big<<<BIG_BLOCKS, 256>>>(mask_gt, priors, box_gt, class_gt, class_p);
    k_override<<<1, 32>>>(class_gt);
    k_selpick<<<SP_BLOCKS, 512>>>(box_gt, class_p, box_p, priors);
    dim3 gk((NPIX_ + 255) / 256, B_);
    k_mask<<<gk, 256>>>(proto_p, coef_p);
    k_final<<<1, 256>>>(out);
}

// round 14
// speedup vs baseline: 1.2052x; 1.2052x over previous
#include <cuda_runtime.h>
#include <math.h>

#define B_    8
#define P_    19248
#define C_    81
#define NOBJ_ 8
#define KC_   32
#define PH_   138
#define PW_   138
#define HH_   550
#define WW_   550
#define NPIX_ (PH_*PW_)
#define MTT_  100
#define SEG3  38   // ceil(P_/512)
#define MBLK  76   // ceil(P_/256)

#define RES_BLOCKS   (B_*PH_)                 // 1104
#define MATCH_BLOCKS (B_*MBLK)                // 608
#define LSE_BLOCKS   ((B_*P_)/8)              // 19248
#define BIG_BLOCKS   (RES_BLOCKS + MATCH_BLOCKS + LSE_BLOCKS)

#define SP_BLOCKS    (16 + B_*MBLK)           // 16 selpick + 608 posloss-role

// ------------------------- device scratch (static) -------------------------
__device__ double             g_acc[2];
__device__ double             g_mlsum[B_];
__device__ unsigned long long g_boxkey[B_][NOBJ_];
__device__ int                g_conf[B_][P_];
__device__ unsigned char      g_pmi[B_][P_];
__device__ float              g_mark[B_][P_];
__device__ float              g_lse[B_][P_];
__device__ int                g_numpos[B_];
__device__ unsigned char      g_dm[B_][NPIX_];
__device__ float              g_wts[PH_][9];
__device__ int                g_wi0[PH_];
__device__ int                g_ones[B_][NOBJ_];
__device__ int                g_sel[B_][MTT_];
__device__ int                g_selcnt[B_];
__device__ int4               g_rect[B_][MTT_];
__device__ float              g_invd[B_][MTT_];
__device__ int                g_obit[B_][MTT_];

// ------------------------- helpers -------------------------
__device__ __forceinline__ float bRedF256(float v) {
    __shared__ float sd[8];
    int ln = threadIdx.x & 31, wd = threadIdx.x >> 5;
    #pragma unroll
    for (int o = 16; o; o >>= 1) v += __shfl_down_sync(0xffffffffu, v, o);
    if (ln == 0) sd[wd] = v;
    __syncthreads();
    v = (threadIdx.x < 8) ? sd[threadIdx.x] : 0.f;
    if (wd == 0) {
        #pragma unroll
        for (int o = 4; o; o >>= 1) v += __shfl_down_sync(0xffffffffu, v, o);
        if (ln == 0) sd[0] = v;
    }
    __syncthreads();
    float r = sd[0];
    __syncthreads();
    return r;
}
__device__ __forceinline__ float bRedF512(float v) {
    __shared__ float sd[16];
    int ln = threadIdx.x & 31, wd = threadIdx.x >> 5;
    #pragma unroll
    for (int o = 16; o; o >>= 1) v += __shfl_down_sync(0xffffffffu, v, o);
    if (ln == 0) sd[wd] = v;
    __syncthreads();
    v = (threadIdx.x < 16) ? sd[threadIdx.x] : 0.f;
    if (wd == 0) {
        #pragma unroll
        for (int o = 8; o; o >>= 1) v += __shfl_down_sync(0xffffffffu, v, o);
        if (ln == 0) sd[0] = v;
    }
    __syncthreads();
    float r = sd[0];
    __syncthreads();
    return r;
}
__device__ __forceinline__ int bRedI512(int v) {
    __shared__ int si[16];
    int ln = threadIdx.x & 31, wd = threadIdx.x >> 5;
    #pragma unroll
    for (int o = 16; o; o >>= 1) v += __shfl_down_sync(0xffffffffu, v, o);
    if (ln == 0) si[wd] = v;
    __syncthreads();
    v = (threadIdx.x < 16) ? si[threadIdx.x] : 0;
    if (wd == 0) {
        #pragma unroll
        for (int o = 8; o; o >>= 1) v += __shfl_down_sync(0xffffffffu, v, o);
        if (ln == 0) si[0] = v;
    }
    __syncthreads();
    int r = si[0];
    __syncthreads();
    return r;
}
__device__ __forceinline__ int bScanEx512(int v, int* sh) {
    int tid = threadIdx.x;
    sh[tid] = v;
    __syncthreads();
    #pragma unroll
    for (int off = 1; off < 512; off <<= 1) {
        int t = (tid >= off) ? sh[tid - off] : 0;
        __syncthreads();
        sh[tid] += t;
        __syncthreads();
    }
    int incl = sh[tid];
    __syncthreads();
    return incl - v;
}

// ------------------------- K0: init (weights + zero accumulators) -------------------------
__global__ void k_init() {
    int t = threadIdx.x;
    if (t < PH_) {
        float inv = (float)(1.0 / (138.0 / 550.0));
        float s = ((float)t + 0.5f) * inv - 0.5f;
        int i0 = (int)ceilf(s - inv);
        int i1 = (int)floorf(s + inv);
        if (i0 < 0) i0 = 0;
        if (i1 > HH_ - 1) i1 = HH_ - 1;
        int cnt = i1 - i0 + 1; if (cnt > 9) cnt = 9;
        float w[9]; float wsum = 0.f;
        #pragma unroll
        for (int k = 0; k < 9; k++) {
            float x = __fdiv_rn(fabsf((float)(i0 + k) - s), inv);
            float wv = fmaxf(0.f, 1.f - x);
            if (k >= cnt) wv = 0.f;
            w[k] = wv; wsum += wv;
        }
        #pragma unroll
        for (int k = 0; k < 9; k++) g_wts[t][k] = __fdiv_rn(w[k], wsum);
        g_wi0[t] = i0;
    }
    if (t < B_ * NOBJ_) {
        ((unsigned long long*)g_boxkey)[t] = 0ull;
        ((int*)g_ones)[t] = 0;
    }
    if (t < B_) { g_numpos[t] = 0; g_mlsum[t] = 0.0; g_selcnt[t] = 0; }
    if (t < 2) g_acc[t] = 0.0;
}

// ------------------------- K1: fused resize + match + lse -------------------------
__global__ void __launch_bounds__(256) k_big(const float* __restrict__ mg,
                                             const float* __restrict__ priors,
                                             const float* __restrict__ box_gt,
                                             const int* __restrict__ class_gt,
                                             const float* __restrict__ class_p) {
    int blk = blockIdx.x;
    int tid = threadIdx.x;
    if (blk < RES_BLOCKS) {
        // ================= resize role =================
        __shared__ float srow[NOBJ_][WW_];
        __shared__ int shc[NOBJ_];
        int b  = blk / PH_;
        int yo = blk % PH_;
        int w  = tid >> 5;
        int lane = tid & 31;
        int i0 = g_wi0[yo];
        float wy[9];
        #pragma unroll
        for (int t = 0; t < 9; t++) wy[t] = g_wts[yo][t];
        if (tid < NOBJ_) shc[tid] = 0;

        const float* src = mg + ((size_t)(b * NOBJ_ + w)) * HH_ * WW_;
        const float2* rows2[9];
        #pragma unroll
        for (int t = 0; t < 9; t++) {
            int yi = i0 + t; if (yi > HH_ - 1) yi = HH_ - 1;
            rows2[t] = (const float2*)(src + (size_t)yi * WW_);
        }
        float2* drow = (float2*)&srow[w][0];
        #pragma unroll 2
        for (int c = lane; c < WW_ / 2; c += 32) {
            float ax = 0.f, ay = 0.f;
            #pragma unroll
            for (int t = 0; t < 9; t++) {
                float2 v = rows2[t][c];
                ax += wy[t] * v.x;
                ay += wy[t] * v.y;
            }
            float2 o2; o2.x = ax; o2.y = ay;
            drow[c] = o2;
        }
        __syncthreads();

        unsigned bits = 0;
        if (tid < PW_) {
            int j0 = g_wi0[tid];
            float wx[9];
            #pragma unroll
            for (int t = 0; t < 9; t++) wx[t] = g_wts[tid][t];
            #pragma unroll
            for (int o = 0; o < NOBJ_; o++) {
                float s = 0.f;
                #pragma unroll
                for (int t = 0; t < 9; t++) {
                    int xi = j0 + t; if (xi > WW_ - 1) xi = WW_ - 1;
                    s += wx[t] * srow[o][xi];
                }
                if (s > 0.5f) bits |= (1u << o);
            }
            g_dm[b][yo * PW_ + tid] = (unsigned char)bits;
        }
        #pragma unroll
        for (int o = 0; o < NOBJ_; o++) {
            unsigned mb = __ballot_sync(0xffffffffu, (bits >> o) & 1);
            if (lane == 0 && mb) atomicAdd(&shc[o], __popc(mb));
        }
        __syncthreads();
        if (tid < NOBJ_ && shc[tid]) atomicAdd(&g_ones[b][tid], shc[tid]);
    } else if (blk < RES_BLOCKS + MATCH_BLOCKS) {
        // ================= match role =================
        int id = blk - RES_BLOCKS;
        int b = id / MBLK;
        int p = (id % MBLK) * 256 + tid;
        bool valid = p < P_;
        int lane = tid & 31;
        __shared__ float sbg[NOBJ_][4];
        __shared__ unsigned long long skey[NOBJ_];
        if (tid < NOBJ_ * 4) ((float*)sbg)[tid] = box_gt[b * NOBJ_ * 4 + tid];
        if (tid < NOBJ_) skey[tid] = 0ull;
        __syncthreads();

        float dx1 = 0.f, dy1 = 0.f, dx2 = 0.f, dy2 = 0.f, areaP = 0.f;
        if (valid) {
            float4 pr = ((const float4*)priors)[p];
            float w2 = __fmul_rn(pr.z, 0.5f), h2 = __fmul_rn(pr.w, 0.5f);
            dx1 = __fsub_rn(pr.x, w2); dy1 = __fsub_rn(pr.y, h2);
            dx2 = __fadd_rn(pr.x, w2); dy2 = __fadd_rn(pr.y, h2);
            areaP = __fmul_rn(__fsub_rn(dx2, dx1), __fsub_rn(dy2, dy1));
        }
        float best = -1.f; int besto = 0;
        #pragma unroll
        for (int o = 0; o < NOBJ_; o++) {
            unsigned u = 0u;
            if (valid) {
                float gx1 = sbg[o][0], gy1 = sbg[o][1], gx2 = sbg[o][2], gy2 = sbg[o][3];
                float ix = fmaxf(__fsub_rn(fminf(gx2, dx2), fmaxf(gx1, dx1)), 0.f);
                float iy = fmaxf(__fsub_rn(fminf(gy2, dy2), fmaxf(gy1, dy1)), 0.f);
                float inter = __fmul_rn(ix, iy);
                float areaG = __fmul_rn(__fsub_rn(gx2, gx1), __fsub_rn(gy2, gy1));
                float iou = __fdiv_rn(inter, __fsub_rn(__fadd_rn(areaG, areaP), inter));
                if (iou > best) { best = iou; besto = o; }
                u = __float_as_uint(iou);
            }
            unsigned wmax = __reduce_max_sync(0xffffffffu, u);
            unsigned bal = __ballot_sync(0xffffffffu, u == wmax);
            int leader = __ffs(bal) - 1;
            if (lane == leader && valid)
                atomicMax(&skey[o], (((unsigned long long)u) << 32)
                                   | (unsigned long long)(0xFFFFFFFFu - (unsigned)p));
        }
        if (valid) {
            int cg = class_gt[b * NOBJ_ + besto];
            int cf = cg + 1;
            if (best < 0.5f) cf = -1;
            if (best < 0.4f) cf = 0;
            g_conf[b][p] = cf;
            g_pmi[b][p]  = (unsigned char)besto;
        }
        __syncthreads();
        if (tid < NOBJ_ && skey[tid]) atomicMax(&g_boxkey[b][tid], skey[tid]);
    } else {
        // ================= lse role =================
        int gw = (blk - RES_BLOCKS - MATCH_BLOCKS) * 8 + (tid >> 5);
        int lane = tid & 31;
        const float* xp = class_p + (size_t)gw * C_;
        float v0 = xp[lane];
        float v1 = xp[lane + 32];
        float v2 = (lane < C_ - 64) ? xp[lane + 64] : 0.f;
        float s = __expf(v0) + __expf(v1);
        if (lane < C_ - 64) s += __expf(v2);
        #pragma unroll
        for (int off = 16; off; off >>= 1) s += __shfl_xor_sync(0xffffffffu, s, off);
        float lse = __logf(s);
        float x0 = __shfl_sync(0xffffffffu, v0, 0);
        if (lane == 0) {
            int b = gw / P_, p = gw % P_;
            g_lse[b][p]  = lse;
            g_mark[b][p] = lse - x0;
        }
    }
}

// ------------------------- K2: forced matches -------------------------
__global__ void k_override(const int* __restrict__ class_gt) {
    int b = threadIdx.x;
    if (b < B_) {
        for (int o = 0; o < NOBJ_; o++) {
            unsigned long long k = g_boxkey[b][o];
            unsigned p = 0xFFFFFFFFu - (unsigned)(k & 0xFFFFFFFFull);
            g_conf[b][p] = class_gt[b * NOBJ_ + o] + 1;
            g_pmi[b][p]  = (unsigned char)o;
        }
    }
}

// ------------------------- K3: select(8) + pick(8) + posloss(608) -------------------------
__global__ void __launch_bounds__(512) k_selpick(const float* __restrict__ box_gt,
                                                 const float* __restrict__ class_p,
                                                 const float* __restrict__ box_p,
                                                 const float* __restrict__ priors) {
    extern __shared__ float smk[];
    __shared__ int hist[256];
    __shared__ int sscan[512];
    __shared__ unsigned sh_prefix;
    __shared__ int sh_rem;
    int tid = threadIdx.x;

    if (blockIdx.x < 8) {
        // ================= select role (computes its own numpos) =================
        int b = blockIdx.x;
        int npl = 0;
        for (int p = tid; p < P_; p += 512) {
            int cf = g_conf[b][p];
            if (cf > 0) npl++;
            smk[p] = (cf == 0) ? g_mark[b][p] : 0.f;
        }
        int np = bRedI512(npl);
        long long kll = 3LL * np; if (kll > P_ - 1) kll = P_ - 1;
        if (kll <= 0) return;
        if (tid == 0) { sh_prefix = 0u; sh_rem = (int)kll; }
        __syncthreads();

        for (int pass = 0; pass < 4; pass++) {
            int shift = 24 - 8 * pass;
            unsigned himask = (pass == 0) ? 0u : (0xFFFFFFFFu << (shift + 8));
            if (tid < 256) hist[tid] = 0;
            __syncthreads();
            unsigned pref = sh_prefix;
            int rem = sh_rem;
            for (int p = tid; p < P_; p += 512) {
                unsigned u = __float_as_uint(smk[p]);
                if ((u & himask) == pref)
                    atomicAdd(&hist[(u >> shift) & 255], 1);
            }
            __syncthreads();
            // parallel suffix-sum bin selection (replaces serial thread-0 scan)
            if (tid < 256) sscan[tid] = hist[tid];
            __syncthreads();
            #pragma unroll
            for (int off = 1; off < 256; off <<= 1) {
                int t = (tid < 256 - off) ? sscan[tid + off] : 0;
                __syncthreads();
                if (tid < 256) sscan[tid] += t;
                __syncthreads();
            }
            if (tid < 256) {
                int s   = sscan[tid];
                int snx = (tid == 255) ? 0 : sscan[tid + 1];
                if (s >= rem && snx < rem) {      // unique: suffix sums are non-increasing
                    sh_rem = rem - snx;
                    sh_prefix = pref | ((unsigned)tid << shift);
                }
            }
            __syncthreads();
        }
        unsigned tb = sh_prefix;
        int quota = sh_rem;

        float sgt = 0.f, seq = 0.f; int ceq = 0;
        for (int p = tid; p < P_; p += 512) {
            float v = smk[p];
            unsigned u = __float_as_uint(v);
            if (u > tb) sgt += v;
            else if (u == tb) { seq += v; ceq++; }
        }
        float sgt_t = bRedF512(sgt);
        float seq_t = bRedF512(seq);
        int   ceq_t = bRedI512(ceq);
        bool ordered = (ceq_t != quota) && (tb != 0u);
        if (tid == 0) atomicAdd(&g_acc[1], (double)(sgt_t + (ordered ? 0.f : seq_t)));

        if (ordered) {
            int s0 = tid * SEG3, s1 = s0 + SEG3; if (s1 > P_) s1 = P_;
            int c = 0;
            for (int p = s0; p < s1; p++)
                if (__float_as_uint(smk[p]) == tb) c++;
            int pre = bScanEx512(c, sscan);
            float sord = 0.f; int r = pre;
            for (int p = s0; p < s1; p++) {
                if (__float_as_uint(smk[p]) == tb) {
                    if (r < quota) sord += smk[p];
                    r++;
                }
            }
            float st = bRedF512(sord);
            if (tid == 0) atomicAdd(&g_acc[1], (double)st);
        }
    } else if (blockIdx.x < 16) {
        // ================= pick role (computes its own numpos) =================
        int b = blockIdx.x - 8;
        int s0 = tid * SEG3, s1 = s0 + SEG3; if (s1 > P_) s1 = P_;
        int c = 0;
        for (int p = s0; p < s1; p++)
            if (g_conf[b][p] > 0) c++;
        int pre = bScanEx512(c, sscan);
        int np = sscan[511];
        int cap = np < MTT_ ? np : MTT_;
        if (tid == 0) { g_numpos[b] = np; g_selcnt[b] = cap; }
        int r = pre;
        for (int p = s0; p < s1; p++) {
            if (g_conf[b][p] > 0) {
                if (r < cap) g_sel[b][r] = p;
                r++;
            }
        }
        __syncthreads();
        for (int k = tid; k < cap; k += 512) {
            int p = g_sel[b][k];
            int o = g_pmi[b][p];
            const float* bg = box_gt + (size_t)(b * NOBJ_ + o) * 4;
            float bx1 = bg[0], by1 = bg[1], bx2 = bg[2], by2 = bg[3];
            float ax = bx1 * 138.f, bx = bx2 * 138.f;
            float x1 = fminf(ax, bx), x2 = fmaxf(ax, bx);
            x1 = fmaxf(x1 - 1.f, 0.f); x2 = fminf(x2 + 1.f, 138.f);
            float ay = by1 * 138.f, by = by2 * 138.f;
            float y1 = fminf(ay, by), y2 = fmaxf(ay, by);
            y1 = fmaxf(y1 - 1.f, 0.f); y2 = fminf(y2 + 1.f, 138.f);
            int xlo = (int)ceilf(x1), xhi = (int)ceilf(x2);
            int ylo = (int)ceilf(y1), yhi = (int)ceilf(y2);
            if (xlo < 0) xlo = 0; if (xhi > PW_) xhi = PW_;
            if (ylo < 0) ylo = 0; if (yhi > PH_) yhi = PH_;
            int4 r4; r4.x = xlo; r4.y = xhi; r4.z = ylo; r4.w = yhi;
            g_rect[b][k] = r4;
            double denom = (double)((bx2 - bx1) * (by2 - by1));
            g_invd[b][k] = (float)(1.0 / denom);
            g_obit[b][k] = o;
        }
    } else {
        // ================= posloss role (256-active of 512) =================
        int id = blockIdx.x - 16;
        int b = id / MBLK;
        int p = (id % MBLK) * 256 + tid;
        int lane = tid & 31;
        bool pos = false;
        int cf = 0;
        if (tid < 256 && p < P_) { cf = g_conf[b][p]; pos = cf > 0; }

        float lb = 0.f, nll = 0.f;
        if (pos) {
            float lse = g_lse[b][p];
            float xt = class_p[((size_t)(b * P_ + p)) * C_ + cf];
            nll = lse - xt;
            int o = g_pmi[b][p];
            const float* bg = box_gt + (size_t)(b * NOBJ_ + o) * 4;
            float mnx = bg[0], mny = bg[1], mxx = bg[2], mxy = bg[3];
            float4 pr = ((const float4*)priors)[p];
            float off0 = __fdiv_rn(__fsub_rn(__fmul_rn(__fadd_rn(mnx, mxx), 0.5f), pr.x), __fmul_rn(0.1f, pr.z));
            float off1 = __fdiv_rn(__fsub_rn(__fmul_rn(__fadd_rn(mny, mxy), 0.5f), pr.y), __fmul_rn(0.1f, pr.w));
            float off2 = __fdiv_rn(logf(__fdiv_rn(__fsub_rn(mxx, mnx), pr.z)), 0.2f);
            float off3 = __fdiv_rn(logf(__fdiv_rn(__fsub_rn(mxy, mny), pr.w)), 0.2f);
            const float4 bp = ((const float4*)box_p)[b * P_ + p];
            float d;
            d = fabsf(bp.x - off0); lb += (d < 1.f) ? 0.5f*d*d : d - 0.5f;
            d = fabsf(bp.y - off1); lb += (d < 1.f) ? 0.5f*d*d : d - 0.5f;
            d = fabsf(bp.z - off2); lb += (d < 1.f) ? 0.5f*d*d : d - 0.5f;
            d = fabsf(bp.w - off3); lb += (d < 1.f) ? 0.5f*d*d : d - 0.5f;
        }
        unsigned bal = __ballot_sync(0xffffffffu, pos);
        #pragma unroll
        for (int off = 16; off; off >>= 1) {
            lb  += __shfl_down_sync(0xffffffffu, lb, off);
            nll += __shfl_down_sync(0xffffffffu, nll, off);
        }
        if (lane == 0 && bal) {
            atomicAdd(&g_acc[0], (double)lb);
            atomicAdd(&g_acc[1], (double)nll);
        }
    }
}

// ------------------------- K4: mask BCE, pixel-centric -------------------------
__global__ void __launch_bounds__(256) k_mask(const float* __restrict__ proto_p,
                                              const float* __restrict__ coef_p) {
    __shared__ float4 scoef[MTT_][8];
    __shared__ int4   srect[MTT_];
    __shared__ float  sinv[MTT_];
    __shared__ int    sob[MTT_];
    int b = blockIdx.y;
    int tid = threadIdx.x;
    int px = blockIdx.x * 256 + tid;
    int cnt = g_selcnt[b];

    for (int i = tid; i < cnt * 8; i += 256) {
        int k = i >> 3, q = i & 7;
        int p = g_sel[b][k];
        scoef[k][q] = ((const float4*)(coef_p + ((size_t)(b * P_ + p)) * KC_))[q];
    }
    for (int i = tid; i < cnt; i += 256) {
        srect[i] = g_rect[b][i];
        sinv[i]  = g_invd[b][i];
        sob[i]   = g_obit[b][i];
    }
    __syncthreads();

    float acc = 0.f;
    if (px < NPIX_ && cnt > 0) {
        int y = px / PW_, x = px % PW_;
        const float4* pp = (const float4*)(proto_p + (size_t)(b * NPIX_ + px) * KC_);
        float4 r0 = pp[0], r1 = pp[1], r2 = pp[2], r3 = pp[3];
        float4 r4 = pp[4], r5 = pp[5], r6 = pp[6], r7 = pp[7];
        unsigned dmb = g_dm[b][px];
        const float L = 16.118095651f;
        const float A  = -logf(1e-7f);
        const float Bc = -log1pf(-1e-7f);
        for (int k = 0; k < cnt; k++) {
            int4 r = srect[k];
            if (x >= r.x && x < r.y && y >= r.z && y < r.w) {
                const float4* ck = scoef[k];
                float4 c0 = ck[0], c1 = ck[1], c2 = ck[2], c3 = ck[3];
                float4 c4 = ck[4], c5 = ck[5], c6 = ck[6], c7 = ck[7];
                float z =
                    r0.x*c0.x + r0.y*c0.y + r0.z*c0.z + r0.w*c0.w +
                    r1.x*c1.x + r1.y*c1.y + r1.z*c1.z + r1.w*c1.w +
                    r2.x*c2.x + r2.y*c2.y + r2.z*c2.z + r2.w*c2.w +
                    r3.x*c3.x + r3.y*c3.y + r3.z*c3.z + r3.w*c3.w +
                    r4.x*c4.x + r4.y*c4.y + r4.z*c4.z + r4.w*c4.w +
                    r5.x*c5.x + r5.y*c5.y + r5.z*c5.z + r5.w*c5.w +
                    r6.x*c6.x + r6.y*c6.y + r6.z*c6.z + r6.w*c6.w +
                    r7.x*c7.x + r7.y*c7.y + r7.z*c7.z + r7.w*c7.w;
                float zc = fminf(fmaxf(z, -L), L);
                float sp = fmaxf(zc, 0.f) + __logf(1.f + __expf(-fabsf(zc)));
                int gt = (dmb >> sob[k]) & 1;
                float vp = sp - (gt ? (zc + A) : Bc);
                acc += vp * sinv[k];
            }
        }
    }
    float t = bRedF256(acc);
    if (tid == 0) atomicAdd(&g_mlsum[b], (double)t);
}

// ------------------------- K5: final combine -------------------------
__global__ void __launch_bounds__(256) k_final(float* out) {
    __shared__ double sd[8];
    int tid = threadIdx.x;
    const float A  = -logf(1e-7f);
    const float Bc = -log1pf(-1e-7f);
    double acc = 0.0;
    for (int i = tid; i < B_ * MTT_; i += 256) {
        int b = i / MTT_, k = i % MTT_;
        if (k < g_selcnt[b]) {
            int o = g_obit[b][k];
            int ones = g_ones[b][o];
            double c = (double)ones * (double)A + (double)(NPIX_ - ones) * (double)Bc;
            int np = g_numpos[b];
            double s = 1.0;
            if (np > MTT_) {
                float npf = (float)np;
                s = (double)(npf / fmaxf(fminf(npf, (float)MTT_), 1.f));
            }
            acc += c * (double)g_invd[b][k] * s;
        }
    }
    if (tid < B_) {
        int np = g_numpos[tid];
        double s = 1.0;
        if (np > MTT_) {
            float npf = (float)np;
            s = (double)(npf / fmaxf(fminf(npf, (float)MTT_), 1.f));
        }
        acc += g_mlsum[tid] * s;
    }
    int ln = tid & 31, wd = tid >> 5;
    #pragma unroll
    for (int o = 16; o; o >>= 1) acc += __shfl_down_sync(0xffffffffu, acc, o);
    if (ln == 0) sd[wd] = acc;
    __syncthreads();
    if (tid < 8) {
        acc = sd[tid];
        #pragma unroll
        for (int o = 4; o; o >>= 1) acc += __shfl_down_sync(0xffffffffu, acc, o);
        if (tid == 0) {
            double total = 1.5 * g_acc[0] + g_acc[1] + acc * 6.125 / 138.0 / 138.0;
            out[0] = (float)total;
        }
    }
}

// ------------------------- launch: 6-node linear chain -------------------------
extern "C" void kernel_launch(void* const* d_in, const int* in_sizes, int n_in,
                              void* d_out, int out_size) {
    const float* class_p  = (const float*)d_in[0];
    const float* box_p    = (const float*)d_in[1];
    const float* coef_p   = (const float*)d_in[2];
    const float* proto_p  = (const float*)d_in[3];
    const float* priors   = (const float*)d_in[4];
    const float* box_gt   = (const float*)d_in[5];
    const float* mask_gt  = (const float*)d_in[6];
    const int*   class_gt = (const int*)d_in[7];
    float* out = (float*)d_out;

    static bool inited = false;
    if (!inited) {
        cudaFuncSetAttribute(k_selpick, cudaFuncAttributeMaxDynamicSharedMemorySize, P_ * 4);
        inited = true;
    }

    k_init<<<1, 256>>>();
    k_big<<<BIG_BLOCKS, 256>>>(mask_gt, priors, box_gt, class_gt, class_p);
    k_override<<<1, 32>>>(class_gt);
    k_selpick<<<SP_BLOCKS, 512, P_ * 4>>>(box_gt, class_p, box_p, priors);
    dim3 gk((NPIX_ + 255) / 256, B_);
    k_mask<<<gk, 256>>>(proto_p, coef_p);
    k_final<<<1, 256>>>(out);
}

// round 15
// speedup vs baseline: 1.2543x; 1.0407x over previous
#include <cuda_runtime.h>
#include <math.h>

#define B_    8
#define P_    19248
#define C_    81
#define NOBJ_ 8
#define KC_   32
#define PH_   138
#define PW_   138
#define HH_   550
#define WW_   550
#define NPIX_ (PH_*PW_)
#define MTT_  100
#define SEG3  38   // ceil(P_/512)
#define MBLK  76   // ceil(P_/256)

#define RES_BLOCKS   (B_*PH_)                 // 1104
#define MATCH_BLOCKS (B_*MBLK)                // 608
#define LSE_BLOCKS   ((B_*P_)/8)              // 19248
#define BIG_BLOCKS   (RES_BLOCKS + MATCH_BLOCKS + LSE_BLOCKS)

#define MPB          76                       // ceil(NPIX_/256) mask blocks per batch = 75 -> use 75
#define MASK_BLOCKS  (B_ * 75)                // 600
#define MK_BLOCKS    (MASK_BLOCKS + B_*MBLK)  // 600 mask + 608 posloss

// ------------------------- device scratch (static) -------------------------
__device__ double             g_acc[2];
__device__ double             g_mlsum[B_];
__device__ unsigned long long g_boxkey[B_][NOBJ_];
__device__ int                g_conf[B_][P_];
__device__ unsigned char      g_pmi[B_][P_];
__device__ float              g_mark[B_][P_];
__device__ float              g_lse[B_][P_];
__device__ int                g_numpos[B_];
__device__ unsigned char      g_dm[B_][NPIX_];
__device__ float              g_wts[PH_][9];
__device__ int                g_wi0[PH_];
__device__ int                g_ones[B_][NOBJ_];
__device__ int                g_sel[B_][MTT_];
__device__ int                g_selcnt[B_];
__device__ int4               g_rect[B_][MTT_];
__device__ float              g_invd[B_][MTT_];
__device__ int                g_obit[B_][MTT_];

// ------------------------- helpers -------------------------
__device__ __forceinline__ float bRedF256(float v) {
    __shared__ float sd[8];
    int ln = threadIdx.x & 31, wd = threadIdx.x >> 5;
    #pragma unroll
    for (int o = 16; o; o >>= 1) v += __shfl_down_sync(0xffffffffu, v, o);
    if (ln == 0) sd[wd] = v;
    __syncthreads();
    v = (threadIdx.x < 8) ? sd[threadIdx.x] : 0.f;
    if (wd == 0) {
        #pragma unroll
        for (int o = 4; o; o >>= 1) v += __shfl_down_sync(0xffffffffu, v, o);
        if (ln == 0) sd[0] = v;
    }
    __syncthreads();
    float r = sd[0];
    __syncthreads();
    return r;
}
__device__ __forceinline__ float bRedF512(float v) {
    __shared__ float sd[16];
    int ln = threadIdx.x & 31, wd = threadIdx.x >> 5;
    #pragma unroll
    for (int o = 16; o; o >>= 1) v += __shfl_down_sync(0xffffffffu, v, o);
    if (ln == 0) sd[wd] = v;
    __syncthreads();
    v = (threadIdx.x < 16) ? sd[threadIdx.x] : 0.f;
    if (wd == 0) {
        #pragma unroll
        for (int o = 8; o; o >>= 1) v += __shfl_down_sync(0xffffffffu, v, o);
        if (ln == 0) sd[0] = v;
    }
    __syncthreads();
    float r = sd[0];
    __syncthreads();
    return r;
}
__device__ __forceinline__ int bRedI512(int v) {
    __shared__ int si[16];
    int ln = threadIdx.x & 31, wd = threadIdx.x >> 5;
    #pragma unroll
    for (int o = 16; o; o >>= 1) v += __shfl_down_sync(0xffffffffu, v, o);
    if (ln == 0) si[wd] = v;
    __syncthreads();
    v = (threadIdx.x < 16) ? si[threadIdx.x] : 0;
    if (wd == 0) {
        #pragma unroll
        for (int o = 8; o; o >>= 1) v += __shfl_down_sync(0xffffffffu, v, o);
        if (ln == 0) si[0] = v;
    }
    __syncthreads();
    int r = si[0];
    __syncthreads();
    return r;
}
__device__ __forceinline__ int bScanEx512(int v, int* sh) {
    int tid = threadIdx.x;
    sh[tid] = v;
    __syncthreads();
    #pragma unroll
    for (int off = 1; off < 512; off <<= 1) {
        int t = (tid >= off) ? sh[tid - off] : 0;
        __syncthreads();
        sh[tid] += t;
        __syncthreads();
    }
    int incl = sh[tid];
    __syncthreads();
    return incl - v;
}

// ------------------------- K0: init (weights + zero accumulators) -------------------------
__global__ void k_init() {
    int t = threadIdx.x;
    if (t < PH_) {
        float inv = (float)(1.0 / (138.0 / 550.0));
        float s = ((float)t + 0.5f) * inv - 0.5f;
        int i0 = (int)ceilf(s - inv);
        int i1 = (int)floorf(s + inv);
        if (i0 < 0) i0 = 0;
        if (i1 > HH_ - 1) i1 = HH_ - 1;
        int cnt = i1 - i0 + 1; if (cnt > 9) cnt = 9;
        float w[9]; float wsum = 0.f;
        #pragma unroll
        for (int k = 0; k < 9; k++) {
            float x = __fdiv_rn(fabsf((float)(i0 + k) - s), inv);
            float wv = fmaxf(0.f, 1.f - x);
            if (k >= cnt) wv = 0.f;
            w[k] = wv; wsum += wv;
        }
        #pragma unroll
        for (int k = 0; k < 9; k++) g_wts[t][k] = __fdiv_rn(w[k], wsum);
        g_wi0[t] = i0;
    }
    if (t < B_ * NOBJ_) {
        ((unsigned long long*)g_boxkey)[t] = 0ull;
        ((int*)g_ones)[t] = 0;
    }
    if (t < B_) { g_numpos[t] = 0; g_mlsum[t] = 0.0; g_selcnt[t] = 0; }
    if (t < 2) g_acc[t] = 0.0;
}

// ------------------------- K1: fused resize + match + lse -------------------------
__global__ void __launch_bounds__(256) k_big(const float* __restrict__ mg,
                                             const float* __restrict__ priors,
                                             const float* __restrict__ box_gt,
                                             const int* __restrict__ class_gt,
                                             const float* __restrict__ class_p) {
    int blk = blockIdx.x;
    int tid = threadIdx.x;
    if (blk < RES_BLOCKS) {
        // ================= resize role =================
        __shared__ float srow[NOBJ_][WW_];
        __shared__ int shc[NOBJ_];
        int b  = blk / PH_;
        int yo = blk % PH_;
        int w  = tid >> 5;
        int lane = tid & 31;
        int i0 = g_wi0[yo];
        float wy[9];
        #pragma unroll
        for (int t = 0; t < 9; t++) wy[t] = g_wts[yo][t];
        if (tid < NOBJ_) shc[tid] = 0;

        const float* src = mg + ((size_t)(b * NOBJ_ + w)) * HH_ * WW_;
        const float2* rows2[9];
        #pragma unroll
        for (int t = 0; t < 9; t++) {
            int yi = i0 + t; if (yi > HH_ - 1) yi = HH_ - 1;
            rows2[t] = (const float2*)(src + (size_t)yi * WW_);
        }
        float2* drow = (float2*)&srow[w][0];
        #pragma unroll 2
        for (int c = lane; c < WW_ / 2; c += 32) {
            float ax = 0.f, ay = 0.f;
            #pragma unroll
            for (int t = 0; t < 9; t++) {
                float2 v = rows2[t][c];
                ax += wy[t] * v.x;
                ay += wy[t] * v.y;
            }
            float2 o2; o2.x = ax; o2.y = ay;
            drow[c] = o2;
        }
        __syncthreads();

        unsigned bits = 0;
        if (tid < PW_) {
            int j0 = g_wi0[tid];
            float wx[9];
            #pragma unroll
            for (int t = 0; t < 9; t++) wx[t] = g_wts[tid][t];
            #pragma unroll
            for (int o = 0; o < NOBJ_; o++) {
                float s = 0.f;
                #pragma unroll
                for (int t = 0; t < 9; t++) {
                    int xi = j0 + t; if (xi > WW_ - 1) xi = WW_ - 1;
                    s += wx[t] * srow[o][xi];
                }
                if (s > 0.5f) bits |= (1u << o);
            }
            g_dm[b][yo * PW_ + tid] = (unsigned char)bits;
        }
        #pragma unroll
        for (int o = 0; o < NOBJ_; o++) {
            unsigned mb = __ballot_sync(0xffffffffu, (bits >> o) & 1);
            if (lane == 0 && mb) atomicAdd(&shc[o], __popc(mb));
        }
        __syncthreads();
        if (tid < NOBJ_ && shc[tid]) atomicAdd(&g_ones[b][tid], shc[tid]);
    } else if (blk < RES_BLOCKS + MATCH_BLOCKS) {
        // ================= match role =================
        int id = blk - RES_BLOCKS;
        int b = id / MBLK;
        int p = (id % MBLK) * 256 + tid;
        bool valid = p < P_;
        int lane = tid & 31;
        __shared__ float sbg[NOBJ_][4];
        __shared__ unsigned long long skey[NOBJ_];
        if (tid < NOBJ_ * 4) ((float*)sbg)[tid] = box_gt[b * NOBJ_ * 4 + tid];
        if (tid < NOBJ_) skey[tid] = 0ull;
        __syncthreads();

        float dx1 = 0.f, dy1 = 0.f, dx2 = 0.f, dy2 = 0.f, areaP = 0.f;
        if (valid) {
            float4 pr = ((const float4*)priors)[p];
            float w2 = __fmul_rn(pr.z, 0.5f), h2 = __fmul_rn(pr.w, 0.5f);
            dx1 = __fsub_rn(pr.x, w2); dy1 = __fsub_rn(pr.y, h2);
            dx2 = __fadd_rn(pr.x, w2); dy2 = __fadd_rn(pr.y, h2);
            areaP = __fmul_rn(__fsub_rn(dx2, dx1), __fsub_rn(dy2, dy1));
        }
        float best = -1.f; int besto = 0;
        #pragma unroll
        for (int o = 0; o < NOBJ_; o++) {
            unsigned u = 0u;
            if (valid) {
                float gx1 = sbg[o][0], gy1 = sbg[o][1], gx2 = sbg[o][2], gy2 = sbg[o][3];
                float ix = fmaxf(__fsub_rn(fminf(gx2, dx2), fmaxf(gx1, dx1)), 0.f);
                float iy = fmaxf(__fsub_rn(fminf(gy2, dy2), fmaxf(gy1, dy1)), 0.f);
                float inter = __fmul_rn(ix, iy);
                float areaG = __fmul_rn(__fsub_rn(gx2, gx1), __fsub_rn(gy2, gy1));
                float iou = __fdiv_rn(inter, __fsub_rn(__fadd_rn(areaG, areaP), inter));
                if (iou > best) { best = iou; besto = o; }
                u = __float_as_uint(iou);
            }
            unsigned wmax = __reduce_max_sync(0xffffffffu, u);
            unsigned bal = __ballot_sync(0xffffffffu, u == wmax);
            int leader = __ffs(bal) - 1;
            if (lane == leader && valid)
                atomicMax(&skey[o], (((unsigned long long)u) << 32)
                                   | (unsigned long long)(0xFFFFFFFFu - (unsigned)p));
        }
        if (valid) {
            int cg = class_gt[b * NOBJ_ + besto];
            int cf = cg + 1;
            if (best < 0.5f) cf = -1;
            if (best < 0.4f) cf = 0;
            g_conf[b][p] = cf;
            g_pmi[b][p]  = (unsigned char)besto;
        }
        __syncthreads();
        if (tid < NOBJ_ && skey[tid]) atomicMax(&g_boxkey[b][tid], skey[tid]);
    } else {
        // ================= lse role =================
        int gw = (blk - RES_BLOCKS - MATCH_BLOCKS) * 8 + (tid >> 5);
        int lane = tid & 31;
        const float* xp = class_p + (size_t)gw * C_;
        float v0 = xp[lane];
        float v1 = xp[lane + 32];
        float v2 = (lane < C_ - 64) ? xp[lane + 64] : 0.f;
        float s = __expf(v0) + __expf(v1);
        if (lane < C_ - 64) s += __expf(v2);
        #pragma unroll
        for (int off = 16; off; off >>= 1) s += __shfl_xor_sync(0xffffffffu, s, off);
        float lse = __logf(s);
        float x0 = __shfl_sync(0xffffffffu, v0, 0);
        if (lane == 0) {
            int b = gw / P_, p = gw % P_;
            g_lse[b][p]  = lse;
            g_mark[b][p] = lse - x0;
        }
    }
}

// ------------------------- K2: forced matches -------------------------
__global__ void k_override(const int* __restrict__ class_gt) {
    int b = threadIdx.x;
    if (b < B_) {
        for (int o = 0; o < NOBJ_; o++) {
            unsigned long long k = g_boxkey[b][o];
            unsigned p = 0xFFFFFFFFu - (unsigned)(k & 0xFFFFFFFFull);
            g_conf[b][p] = class_gt[b * NOBJ_ + o] + 1;
            g_pmi[b][p]  = (unsigned char)o;
        }
    }
}

// ------------------------- K3: select(8) + pick(8) -------------------------
__global__ void __launch_bounds__(512) k_selpick(const float* __restrict__ box_gt) {
    extern __shared__ float smk[];
    __shared__ int hist[256];
    __shared__ int sscan[512];
    __shared__ unsigned sh_prefix;
    __shared__ int sh_rem;
    int tid = threadIdx.x;

    if (blockIdx.x < 8) {
        // ================= select role (computes its own numpos) =================
        int b = blockIdx.x;
        int npl = 0;
        for (int p = tid; p < P_; p += 512) {
            int cf = g_conf[b][p];
            if (cf > 0) npl++;
            smk[p] = (cf == 0) ? g_mark[b][p] : 0.f;
        }
        int np = bRedI512(npl);
        long long kll = 3LL * np; if (kll > P_ - 1) kll = P_ - 1;
        if (kll <= 0) return;
        if (tid == 0) { sh_prefix = 0u; sh_rem = (int)kll; }
        __syncthreads();

        for (int pass = 0; pass < 4; pass++) {
            int shift = 24 - 8 * pass;
            unsigned himask = (pass == 0) ? 0u : (0xFFFFFFFFu << (shift + 8));
            if (tid < 256) hist[tid] = 0;
            __syncthreads();
            unsigned pref = sh_prefix;
            int rem = sh_rem;
            for (int p = tid; p < P_; p += 512) {
                unsigned u = __float_as_uint(smk[p]);
                if ((u & himask) == pref)
                    atomicAdd(&hist[(u >> shift) & 255], 1);
            }
            __syncthreads();
            // parallel suffix-sum bin selection
            if (tid < 256) sscan[tid] = hist[tid];
            __syncthreads();
            #pragma unroll
            for (int off = 1; off < 256; off <<= 1) {
                int t = (tid < 256 - off) ? sscan[tid + off] : 0;
                __syncthreads();
                if (tid < 256) sscan[tid] += t;
                __syncthreads();
            }
            if (tid < 256) {
                int s   = sscan[tid];
                int snx = (tid == 255) ? 0 : sscan[tid + 1];
                if (s >= rem && snx < rem) {
                    sh_rem = rem - snx;
                    sh_prefix = pref | ((unsigned)tid << shift);
                }
            }
            __syncthreads();
        }
        unsigned tb = sh_prefix;
        int quota = sh_rem;

        float sgt = 0.f, seq = 0.f; int ceq = 0;
        for (int p = tid; p < P_; p += 512) {
            float v = smk[p];
            unsigned u = __float_as_uint(v);
            if (u > tb) sgt += v;
            else if (u == tb) { seq += v; ceq++; }
        }
        float sgt_t = bRedF512(sgt);
        float seq_t = bRedF512(seq);
        int   ceq_t = bRedI512(ceq);
        bool ordered = (ceq_t != quota) && (tb != 0u);
        if (tid == 0) atomicAdd(&g_acc[1], (double)(sgt_t + (ordered ? 0.f : seq_t)));

        if (ordered) {
            int s0 = tid * SEG3, s1 = s0 + SEG3; if (s1 > P_) s1 = P_;
            int c = 0;
            for (int p = s0; p < s1; p++)
                if (__float_as_uint(smk[p]) == tb) c++;
            int pre = bScanEx512(c, sscan);
            float sord = 0.f; int r = pre;
            for (int p = s0; p < s1; p++) {
                if (__float_as_uint(smk[p]) == tb) {
                    if (r < quota) sord += smk[p];
                    r++;
                }
            }
            float st = bRedF512(sord);
            if (tid == 0) atomicAdd(&g_acc[1], (double)st);
        }
    } else {
        // ================= pick role (computes its own numpos) =================
        int b = blockIdx.x - 8;
        int s0 = tid * SEG3, s1 = s0 + SEG3; if (s1 > P_) s1 = P_;
        int c = 0;
        for (int p = s0; p < s1; p++)
            if (g_conf[b][p] > 0) c++;
        int pre = bScanEx512(c, sscan);
        int np = sscan[511];
        int cap = np < MTT_ ? np : MTT_;
        if (tid == 0) { g_numpos[b] = np; g_selcnt[b] = cap; }
        int r = pre;
        for (int p = s0; p < s1; p++) {
            if (g_conf[b][p] > 0) {
                if (r < cap) g_sel[b][r] = p;
                r++;
            }
        }
        __syncthreads();
        for (int k = tid; k < cap; k += 512) {
            int p = g_sel[b][k];
            int o = g_pmi[b][p];
            const float* bg = box_gt + (size_t)(b * NOBJ_ + o) * 4;
            float bx1 = bg[0], by1 = bg[1], bx2 = bg[2], by2 = bg[3];
            float ax = bx1 * 138.f, bx = bx2 * 138.f;
            float x1 = fminf(ax, bx), x2 = fmaxf(ax, bx);
            x1 = fmaxf(x1 - 1.f, 0.f); x2 = fminf(x2 + 1.f, 138.f);
            float ay = by1 * 138.f, by = by2 * 138.f;
            float y1 = fminf(ay, by), y2 = fmaxf(ay, by);
            y1 = fmaxf(y1 - 1.f, 0.f); y2 = fminf(y2 + 1.f, 138.f);
            int xlo = (int)ceilf(x1), xhi = (int)ceilf(x2);
            int ylo = (int)ceilf(y1), yhi = (int)ceilf(y2);
            if (xlo < 0) xlo = 0; if (xhi > PW_) xhi = PW_;
            if (ylo < 0) ylo = 0; if (yhi > PH_) yhi = PH_;
            int4 r4; r4.x = xlo; r4.y = xhi; r4.z = ylo; r4.w = yhi;
            g_rect[b][k] = r4;
            double denom = (double)((bx2 - bx1) * (by2 - by1));
            g_invd[b][k] = (float)(1.0 / denom);
            g_obit[b][k] = o;
        }
    }
}

// ------------------------- K4: mask BCE (600 blocks) + posloss (608 blocks) -------------------------
__global__ void __launch_bounds__(256) k_mask(const float* __restrict__ proto_p,
                                              const float* __restrict__ coef_p,
                                              const float* __restrict__ class_p,
                                              const float* __restrict__ box_p,
                                              const float* __restrict__ priors,
                                              const float* __restrict__ box_gt) {
    int tid = threadIdx.x;
    if (blockIdx.x < MASK_BLOCKS) {
        // ================= mask role =================
        __shared__ float4 scoef[MTT_][8];
        __shared__ int4   srect[MTT_];
        __shared__ float  sinv[MTT_];
        __shared__ int    sob[MTT_];
        int b  = blockIdx.x / 75;
        int px = (blockIdx.x % 75) * 256 + tid;
        int cnt = g_selcnt[b];

        for (int i = tid; i < cnt * 8; i += 256) {
            int k = i >> 3, q = i & 7;
            int p = g_sel[b][k];
            scoef[k][q] = ((const float4*)(coef_p + ((size_t)(b * P_ + p)) * KC_))[q];
        }
        for (int i = tid; i < cnt; i += 256) {
            srect[i] = g_rect[b][i];
            sinv[i]  = g_invd[b][i];
            sob[i]   = g_obit[b][i];
        }
        __syncthreads();

        float acc = 0.f;
        if (px < NPIX_ && cnt > 0) {
            int y = px / PW_, x = px % PW_;
            const float4* pp = (const float4*)(proto_p + (size_t)(b * NPIX_ + px) * KC_);
            float4 r0 = pp[0], r1 = pp[1], r2 = pp[2], r3 = pp[3];
            float4 r4 = pp[4], r5 = pp[5], r6 = pp[6], r7 = pp[7];
            unsigned dmb = g_dm[b][px];
            const float L = 16.118095651f;
            const float A  = -logf(1e-7f);
            const float Bc = -log1pf(-1e-7f);
            for (int k = 0; k < cnt; k++) {
                int4 r = srect[k];
                if (x >= r.x && x < r.y && y >= r.z && y < r.w) {
                    const float4* ck = scoef[k];
                    float4 c0 = ck[0], c1 = ck[1], c2 = ck[2], c3 = ck[3];
                    float4 c4 = ck[4], c5 = ck[5], c6 = ck[6], c7 = ck[7];
                    float z =
                        r0.x*c0.x + r0.y*c0.y + r0.z*c0.z + r0.w*c0.w +
                        r1.x*c1.x + r1.y*c1.y + r1.z*c1.z + r1.w*c1.w +
                        r2.x*c2.x + r2.y*c2.y + r2.z*c2.z + r2.w*c2.w +
                        r3.x*c3.x + r3.y*c3.y + r3.z*c3.z + r3.w*c3.w +
                        r4.x*c4.x + r4.y*c4.y + r4.z*c4.z + r4.w*c4.w +
                        r5.x*c5.x + r5.y*c5.y + r5.z*c5.z + r5.w*c5.w +
                        r6.x*c6.x + r6.y*c6.y + r6.z*c6.z + r6.w*c6.w +
                        r7.x*c7.x + r7.y*c7.y + r7.z*c7.z + r7.w*c7.w;
                    float zc = fminf(fmaxf(z, -L), L);
                    float sp = fmaxf(zc, 0.f) + __logf(1.f + __expf(-fabsf(zc)));
                    int gt = (dmb >> sob[k]) & 1;
                    float vp = sp - (gt ? (zc + A) : Bc);
                    acc += vp * sinv[k];
                }
            }
        }
        float t = bRedF256(acc);
        if (tid == 0) atomicAdd(&g_mlsum[b], (double)t);
    } else {
        // ================= posloss role =================
        int id = blockIdx.x - MASK_BLOCKS;
        int b = id / MBLK;
        int p = (id % MBLK) * 256 + tid;
        int lane = tid & 31;
        bool pos = false;
        int cf = 0;
        if (p < P_) { cf = g_conf[b][p]; pos = cf > 0; }

        float lb = 0.f, nll = 0.f;
        if (pos) {
            float lse = g_lse[b][p];
            float xt = class_p[((size_t)(b * P_ + p)) * C_ + cf];
            nll = lse - xt;
            int o = g_pmi[b][p];
            const float* bg = box_gt + (size_t)(b * NOBJ_ + o) * 4;
            float mnx = bg[0], mny = bg[1], mxx = bg[2], mxy = bg[3];
            float4 pr = ((const float4*)priors)[p];
            float off0 = __fdiv_rn(__fsub_rn(__fmul_rn(__fadd_rn(mnx, mxx), 0.5f), pr.x), __fmul_rn(0.1f, pr.z));
            float off1 = __fdiv_rn(__fsub_rn(__fmul_rn(__fadd_rn(mny, mxy), 0.5f), pr.y), __fmul_rn(0.1f, pr.w));
            float off2 = __fdiv_rn(logf(__fdiv_rn(__fsub_rn(mxx, mnx), pr.z)), 0.2f);
            float off3 = __fdiv_rn(logf(__fdiv_rn(__fsub_rn(mxy, mny), pr.w)), 0.2f);
            const float4 bp = ((const float4*)box_p)[b * P_ + p];
            float d;
            d = fabsf(bp.x - off0); lb += (d < 1.f) ? 0.5f*d*d : d - 0.5f;
            d = fabsf(bp.y - off1); lb += (d < 1.f) ? 0.5f*d*d : d - 0.5f;
            d = fabsf(bp.z - off2); lb += (d < 1.f) ? 0.5f*d*d : d - 0.5f;
            d = fabsf(bp.w - off3); lb += (d < 1.f) ? 0.5f*d*d : d - 0.5f;
        }
        unsigned bal = __ballot_sync(0xffffffffu, pos);
        #pragma unroll
        for (int off = 16; off; off >>= 1) {
            lb  += __shfl_down_sync(0xffffffffu, lb, off);
            nll += __shfl_down_sync(0xffffffffu, nll, off);
        }
        if (lane == 0 && bal) {
            atomicAdd(&g_acc[0], (double)lb);
            atomicAdd(&g_acc[1], (double)nll);
        }
    }
}

// ------------------------- K5: final combine -------------------------
__global__ void __launch_bounds__(256) k_final(float* out) {
    __shared__ double sd[8];
    int tid = threadIdx.x;
    const float A  = -logf(1e-7f);
    const float Bc = -log1pf(-1e-7f);
    double acc = 0.0;
    for (int i = tid; i < B_ * MTT_; i += 256) {
        int b = i / MTT_, k = i % MTT_;
        if (k < g_selcnt[b]) {
            int o = g_obit[b][k];
            int ones = g_ones[b][o];
            double c = (double)ones * (double)A + (double)(NPIX_ - ones) * (double)Bc;
            int np = g_numpos[b];
            double s = 1.0;
            if (np > MTT_) {
                float npf = (float)np;
                s = (double)(npf / fmaxf(fminf(npf, (float)MTT_), 1.f));
            }
            acc += c * (double)g_invd[b][k] * s;
        }
    }
    if (tid < B_) {
        int np = g_numpos[tid];
        double s = 1.0;
        if (np > MTT_) {
            float npf = (float)np;
            s = (double)(npf / fmaxf(fminf(npf, (float)MTT_), 1.f));
        }
        acc += g_mlsum[tid] * s;
    }
    int ln = tid & 31, wd = tid >> 5;
    #pragma unroll
    for (int o = 16; o; o >>= 1) acc += __shfl_down_sync(0xffffffffu, acc, o);
    if (ln == 0) sd[wd] = acc;
    __syncthreads();
    if (tid < 8) {
        acc = sd[tid];
        #pragma unroll
        for (int o = 4; o; o >>= 1) acc += __shfl_down_sync(0xffffffffu, acc, o);
        if (tid == 0) {
            double total = 1.5 * g_acc[0] + g_acc[1] + acc * 6.125 / 138.0 / 138.0;
            out[0] = (float)total;
        }
    }
}

// ------------------------- launch: 6-node linear chain -------------------------
extern "C" void kernel_launch(void* const* d_in, const int* in_sizes, int n_in,
                              void* d_out, int out_size) {
    const float* class_p  = (const float*)d_in[0];
    const float* box_p    = (const float*)d_in[1];
    const float* coef_p   = (const float*)d_in[2];
    const float* proto_p  = (const float*)d_in[3];
    const float* priors   = (const float*)d_in[4];
    const float* box_gt   = (const float*)d_in[5];
    const float* mask_gt  = (const float*)d_in[6];
    const int*   class_gt = (const int*)d_in[7];
    float* out = (float*)d_out;

    static bool inited = false;
    if (!inited) {
        cudaFuncSetAttribute(k_selpick, cudaFuncAttributeMaxDynamicSharedMemorySize, P_ * 4);
        inited = true;
    }

    k_init<<<1, 256>>>();
    k_big<<<BIG_BLOCKS, 256>>>(mask_gt, priors, box_gt, class_gt, class_p);
    k_override<<<1, 32>>>(class_gt);
    k_selpick<<<16, 512, P_ * 4>>>(box_gt);
    k_mask<<<MK_BLOCKS, 256>>>(proto_p, coef_p, class_p, box_p, priors, box_gt);
    k_final<<<1, 256>>>(out);
}